// round 11
// baseline (speedup 1.0000x reference)
#include <cuda_runtime.h>
#include <cuda_bf16.h>

// ============================================================================
// ESN: FFT(2^18) -> proj(32->50) -> chunked tanh scan -> proj(50->32) -> IFFT.
// R11: fixes k_inv1_out L1tex bottleneck (74% L1, 13.1M broadcast wavefronts)
// by staging g_states tiles into smem with coalesced cooperative loads.
// Numerics bit-identical to R10.
// ============================================================================

#define T_LEN   262144
#define R_DIM   50
#define IN_C    32

#define CH      64      // scan chunk length
#define WARM    32      // warm-up steps per chunk

#define NBUF    (T_LEN * 32)        // 8388608
#define NPROJ   (T_LEN * R_DIM)     // 13107200

// dynamic smem layout: float2 sd[32*513] | float2 twid[256] | float wsm[1600]
//                      | float2 ss[64*50] (inv1 only)
#define SD_ELEMS   (32 * 513)
#define SMEM_FFT   ((SD_ELEMS + 256) * 8)                 // 133376 B
#define SMEM_FUSED (SMEM_FFT + 1600 * 4)                  // 139776 B
#define SMEM_INV1  (SMEM_FUSED + 64 * 50 * 8)             // 165376 B

__device__ float2 g_buf0[NBUF];     // 67 MB (fwd1 -> fwd2)
__device__ float2 g_buf1[NBUF];     // 67 MB (inv1 -> inv2)
__device__ float2 g_proj[NPROJ];    // 105 MB
__device__ float2 g_states[NPROJ];  // 105 MB

// ---------------------------------------------------------------------------
// 512-pt radix-2 DIT FFT on 32 smem columns; column owned by one warp.
// Input bit-reversed. twid[j] = (cos(pi j/256), sin(pi j/256)); stage st uses
// idx = pos << (9-st). SGN=-1 fwd, +1 inv.
// ---------------------------------------------------------------------------
template <int SGN>
__device__ __forceinline__ void fft512_block(float2* sd, const float2* twid, int tid) {
    int col  = tid >> 5;
    int lane = tid & 31;
    float2* s = sd + col * 513;
#pragma unroll
    for (int st = 1; st <= 9; ++st) {
        int half = 1 << (st - 1);
#pragma unroll
        for (int p = 0; p < 8; ++p) {
            int b   = lane + (p << 5);          // butterfly 0..255
            int grp = b >> (st - 1);
            int pos = b & (half - 1);
            int i0  = grp * (half << 1) + pos;
            int i1  = i0 + half;
            float2 w = twid[pos << (9 - st)];
            float cw = w.x;
            float sw = (SGN < 0) ? -w.y : w.y;
            float2 a = s[i0], bb = s[i1];
            float tx = bb.x * cw - bb.y * sw;
            float ty = bb.x * sw + bb.y * cw;
            s[i0] = make_float2(a.x + tx, a.y + ty);
            s[i1] = make_float2(a.x - tx, a.y - ty);
        }
        __syncwarp();
    }
}

#define TWID_INIT()                                                          \
    if (tid < 256) {                                                         \
        float swv, cwv;                                                      \
        sincospif((float)tid * (1.0f / 256.0f), &swv, &cwv);                 \
        twid[tid] = make_float2(cwv, swv);                                   \
    }

// ---------------------------------------------------------------------------
// fwd pass 1: per n2, FFT over n1 (rows n2+512j), inter-pass twiddle
// exp(-2pi*i*n2*k1/N) [exact dyadic sincospif], store transposed (256B rows).
// ---------------------------------------------------------------------------
__global__ void __launch_bounds__(1024) k_fwd1(const float* __restrict__ src) {
    extern __shared__ char smraw[];
    float2* sd   = (float2*)smraw;
    float2* twid = sd + SD_ELEMS;
    int tid = threadIdx.x;
    TWID_INIT();
    int n2 = blockIdx.x;
    int cc = tid & 31, rb = tid >> 5;

#pragma unroll
    for (int q = 0; q < 16; ++q) {
        int j = rb + (q << 5);
        float v = src[(n2 + (j << 9)) * 32 + cc];          // 128B/warp
        sd[cc * 513 + (__brev((unsigned)j) >> 23)] = make_float2(v, 0.f);
    }
    __syncthreads();

    fft512_block<-1>(sd, twid, tid);
    __syncthreads();

#pragma unroll
    for (int q = 0; q < 16; ++q) {
        int k1 = rb + (q << 5);
        float2 v = sd[cc * 513 + k1];
        float frac = -(float)(n2 * k1) * (2.0f / 262144.f);   // exact dyadic
        float sw, cw; sincospif(frac, &sw, &cw);
        g_buf0[((k1 << 9) + n2) * 32 + cc] =                   // 256B/warp
            make_float2(v.x * cw - v.y * sw, v.x * sw + v.y * cw);
    }
}

// ---------------------------------------------------------------------------
// fwd pass 2 + proj fused: per k1, FFT over contiguous rows, then
// proj[t,r] = sum_c FFT(X)[t,c]*Win[r,c] straight from smem.
// One warp per row; lane covers r and r+32.
// ---------------------------------------------------------------------------
__global__ void __launch_bounds__(1024) k_fwd2_proj(const float* __restrict__ Win) {
    extern __shared__ char smraw[];
    float2* sd   = (float2*)smraw;
    float2* twid = sd + SD_ELEMS;
    float*  wsm  = (float*)(twid + 256);        // wsm[c*50 + r]
    int tid = threadIdx.x;
    TWID_INIT();
    for (int i = tid; i < R_DIM * 32; i += 1024) {
        int r = i >> 5, c = i & 31;             // Win[r*32+c]
        wsm[c * 50 + r] = Win[i];
    }
    int k1 = blockIdx.x;
    int cc = tid & 31, rb = tid >> 5;

#pragma unroll
    for (int q = 0; q < 16; ++q) {
        int j = rb + (q << 5);
        sd[cc * 513 + (__brev((unsigned)j) >> 23)] = g_buf0[((k1 << 9) + j) * 32 + cc];
    }
    __syncthreads();

    fft512_block<-1>(sd, twid, tid);
    __syncthreads();

    int wid = tid >> 5, lane = tid & 31;
    int r0 = lane;
    int r1c = (lane + 32 < R_DIM) ? lane + 32 : R_DIM - 1;
    bool has1 = (lane + 32 < R_DIM);
    for (int rr = wid; rr < 512; rr += 32) {
        float ax0 = 0.f, ax1 = 0.f, ax2 = 0.f, ax3 = 0.f;
        float ay0 = 0.f, ay1 = 0.f, ay2 = 0.f, ay3 = 0.f;
        float bx0 = 0.f, bx1 = 0.f, bx2 = 0.f, bx3 = 0.f;
        float by0 = 0.f, by1 = 0.f, by2 = 0.f, by3 = 0.f;
#pragma unroll
        for (int c = 0; c < 32; c += 4) {
            float2 v0 = sd[(c + 0) * 513 + rr];
            float2 v1 = sd[(c + 1) * 513 + rr];
            float2 v2 = sd[(c + 2) * 513 + rr];
            float2 v3 = sd[(c + 3) * 513 + rr];
            float w0 = wsm[(c + 0) * 50 + r0], u0 = wsm[(c + 0) * 50 + r1c];
            float w1 = wsm[(c + 1) * 50 + r0], u1 = wsm[(c + 1) * 50 + r1c];
            float w2 = wsm[(c + 2) * 50 + r0], u2 = wsm[(c + 2) * 50 + r1c];
            float w3 = wsm[(c + 3) * 50 + r0], u3 = wsm[(c + 3) * 50 + r1c];
            ax0 = fmaf(w0, v0.x, ax0); ay0 = fmaf(w0, v0.y, ay0);
            ax1 = fmaf(w1, v1.x, ax1); ay1 = fmaf(w1, v1.y, ay1);
            ax2 = fmaf(w2, v2.x, ax2); ay2 = fmaf(w2, v2.y, ay2);
            ax3 = fmaf(w3, v3.x, ax3); ay3 = fmaf(w3, v3.y, ay3);
            bx0 = fmaf(u0, v0.x, bx0); by0 = fmaf(u0, v0.y, by0);
            bx1 = fmaf(u1, v1.x, bx1); by1 = fmaf(u1, v1.y, by1);
            bx2 = fmaf(u2, v2.x, bx2); by2 = fmaf(u2, v2.y, by2);
            bx3 = fmaf(u3, v3.x, bx3); by3 = fmaf(u3, v3.y, by3);
        }
        long t = (long)(k1 + (rr << 9));
        g_proj[t * R_DIM + r0] =
            make_float2((ax0 + ax1) + (ax2 + ax3), (ay0 + ay1) + (ay2 + ay3));
        if (has1)
            g_proj[t * R_DIM + lane + 32] =
                make_float2((bx0 + bx1) + (bx2 + bx3), (by0 + by1) + (by2 + by3));
    }
}

// ---------------------------------------------------------------------------
// Chunked reservoir scan (unchanged).
// ---------------------------------------------------------------------------
__device__ __forceinline__ void esn_step(float2 pv, float d, float& sx, float& sy) {
    float zx  = fmaf(d, sx, pv.x);
    float zy  = fmaf(d, sy, pv.y);
    float xcl = fminf(fmaxf(zx, -20.f), 20.f);
    float x2  = xcl + xcl;
    float e   = __expf(x2);
    float em  = __expf(-x2);
    float y2  = zy + zy;
    float kf  = rintf(y2 * 0.15915494309189535f);
    float yr  = fmaf(kf, -6.28125f, y2);
    yr        = fmaf(kf, -1.9353071795864769e-3f, yr);
    float s2, c2; __sincosf(yr, &s2, &c2);
    float den = fmaf(0.5f, e + em, c2);
    float inv = __fdividef(1.f, den);
    sx = 0.5f * (e - em) * inv;
    sy = s2 * inv;
}

__global__ void __launch_bounds__(64) scan_kernel(const float* __restrict__ dv) {
    int r = threadIdx.x;
    if (r >= R_DIM) return;
    float d = dv[r];
    int start = blockIdx.x * CH;
    int ws = start - WARM; if (ws < 0) ws = 0;
    float sx = 0.f, sy = 0.f;

#pragma unroll 4
    for (int t = ws; t < start; ++t) {
        float2 pv = g_proj[t * R_DIM + r];
        esn_step(pv, d, sx, sy);
    }
#pragma unroll 4
    for (int t = start; t < start + CH; ++t) {
        float2 pv = g_proj[t * R_DIM + r];
        esn_step(pv, d, sx, sy);
        g_states[t * R_DIM + r] = make_float2(sx, sy);
    }
}

// ---------------------------------------------------------------------------
// outproj + inv pass 1 fused. R11: states staged through smem in 64-row
// tiles with coalesced cooperative loads (kills the 8B-broadcast L1tex
// bottleneck). Compute order identical to R10.
// ---------------------------------------------------------------------------
__global__ void __launch_bounds__(1024) k_inv1_out(const float* __restrict__ Wout) {
    extern __shared__ char smraw[];
    float2* sd   = (float2*)smraw;
    float2* twid = sd + SD_ELEMS;
    float*  wsm  = (float*)(twid + 256);        // wsm[r*32 + c]
    float2* ss   = (float2*)(wsm + 1600);       // ss[64*50]
    int tid = threadIdx.x;
    TWID_INIT();
    for (int i = tid; i < 32 * R_DIM; i += 1024) {
        int c = i / R_DIM, r = i - c * R_DIM;   // Wout[c*50+r]
        wsm[r * 32 + c] = Wout[i];
    }

    int n2 = blockIdx.x;
    int wid = tid >> 5, lane = tid & 31;        // lane = output column c

    for (int tile = 0; tile < 8; ++tile) {
        int rr0 = tile << 6;                    // 64 rows per tile
        __syncthreads();                        // ss reuse + (tile0) wsm ready
        // coalesced stage: row is 400B contiguous; consecutive threads -> consecutive r
        for (int i = tid; i < 64 * R_DIM; i += 1024) {
            int row = i / R_DIM, r = i - row * R_DIM;
            ss[i] = g_states[(long)(n2 + ((rr0 + row) << 9)) * R_DIM + r];
        }
        __syncthreads();

        // 32 warps x 2 rows each; smem broadcast reads are conflict-free
#pragma unroll
        for (int k = 0; k < 2; ++k) {
            int rl = (wid << 1) + k;            // local row 0..63
            const float2* sp = ss + rl * R_DIM;
            float ax0 = 0.f, ax1 = 0.f, ay0 = 0.f, ay1 = 0.f;
#pragma unroll
            for (int r = 0; r < R_DIM; r += 2) {
                float2 v0 = sp[r];
                float  w0 = wsm[r * 32 + lane];
                ax0 = fmaf(w0, v0.x, ax0); ay0 = fmaf(w0, v0.y, ay0);
                float2 v1 = sp[r + 1];
                float  w1 = wsm[(r + 1) * 32 + lane];
                ax1 = fmaf(w1, v1.x, ax1); ay1 = fmaf(w1, v1.y, ay1);
            }
            int rr = rr0 + rl;
            sd[lane * 513 + (__brev((unsigned)rr) >> 23)] =
                make_float2(ax0 + ax1, ay0 + ay1);
        }
    }
    __syncthreads();

    fft512_block<1>(sd, twid, tid);
    __syncthreads();

    int cc = tid & 31, rb = tid >> 5;
#pragma unroll
    for (int q = 0; q < 16; ++q) {
        int k1 = rb + (q << 5);
        float2 v = sd[cc * 513 + k1];
        float frac = (float)(n2 * k1) * (2.0f / 262144.f);    // exact dyadic
        float sw, cw; sincospif(frac, &sw, &cw);
        g_buf1[((k1 << 9) + n2) * 32 + cc] =
            make_float2(v.x * cw - v.y * sw, v.x * sw + v.y * cw);
    }
}

// ---------------------------------------------------------------------------
// inv pass 2: per k1, FFT over contiguous rows, scale 1/N, write d_out.
// interleaved=1: (re,im) float2; 0: real part only. Stores bounded by n_out.
// ---------------------------------------------------------------------------
__global__ void __launch_bounds__(1024) k_inv2(float* __restrict__ dstf,
                                               int n_out, int interleaved) {
    extern __shared__ char smraw[];
    float2* sd   = (float2*)smraw;
    float2* twid = sd + SD_ELEMS;
    int tid = threadIdx.x;
    TWID_INIT();
    int k1 = blockIdx.x;
    int cc = tid & 31, rb = tid >> 5;

#pragma unroll
    for (int q = 0; q < 16; ++q) {
        int j = rb + (q << 5);
        sd[cc * 513 + (__brev((unsigned)j) >> 23)] = g_buf1[((k1 << 9) + j) * 32 + cc];
    }
    __syncthreads();

    fft512_block<1>(sd, twid, tid);
    __syncthreads();

    const float scale = 1.f / 262144.f;
    if (interleaved) {
        float2* d2 = reinterpret_cast<float2*>(dstf);
#pragma unroll
        for (int q = 0; q < 16; ++q) {
            int k2 = rb + (q << 5);
            float2 v = sd[cc * 513 + k2];
            int idx = (k1 + (k2 << 9)) * 32 + cc;
            if (2 * idx + 1 < n_out)
                d2[idx] = make_float2(v.x * scale, v.y * scale);
        }
    } else {
#pragma unroll
        for (int q = 0; q < 16; ++q) {
            int k2 = rb + (q << 5);
            float2 v = sd[cc * 513 + k2];
            int idx = (k1 + (k2 << 9)) * 32 + cc;
            if (idx < n_out)
                dstf[idx] = v.x * scale;
        }
    }
}

// ---------------------------------------------------------------------------
extern "C" void kernel_launch(void* const* d_in, const int* in_sizes, int n_in,
                              void* d_out, int out_size) {
    const float* X    = nullptr;
    const float* Win  = nullptr;
    const float* dres = nullptr;
    const float* Wout = nullptr;
    for (int i = 0; i < n_in; ++i) {
        int sz = in_sizes[i];
        const float* p = (const float*)d_in[i];
        if (sz == T_LEN * IN_C && !X)          X = p;
        else if (sz == R_DIM && !dres)         dres = p;
        else if (sz == R_DIM * IN_C)           { if (!Win) Win = p; else if (!Wout) Wout = p; }
    }
    if ((!X || !Win || !dres || !Wout) && n_in >= 4) {
        X    = (const float*)d_in[0];
        Win  = (const float*)d_in[1];
        dres = (const float*)d_in[2];
        Wout = (const float*)d_in[3];
        if (in_sizes[0] != T_LEN * IN_C) { X = nullptr; }
    }
    if (!X || !Win || !dres || !Wout || !d_out)
        return;   // fail-closed

    int interleaved = (out_size >= 2 * NBUF) ? 1 : 0;

    cudaFuncSetAttribute(k_fwd1,      cudaFuncAttributeMaxDynamicSharedMemorySize, SMEM_FFT);
    cudaFuncSetAttribute(k_fwd2_proj, cudaFuncAttributeMaxDynamicSharedMemorySize, SMEM_FUSED);
    cudaFuncSetAttribute(k_inv1_out,  cudaFuncAttributeMaxDynamicSharedMemorySize, SMEM_INV1);
    cudaFuncSetAttribute(k_inv2,      cudaFuncAttributeMaxDynamicSharedMemorySize, SMEM_FFT);

    k_fwd1<<<512, 1024, SMEM_FFT>>>(X);                    // X -> buf0
    k_fwd2_proj<<<512, 1024, SMEM_FUSED>>>(Win);           // buf0 -> g_proj
    scan_kernel<<<T_LEN / CH, 64>>>(dres);                 // g_proj -> g_states
    k_inv1_out<<<512, 1024, SMEM_INV1>>>(Wout);            // g_states -> buf1
    k_inv2<<<512, 1024, SMEM_FFT>>>((float*)d_out, out_size, interleaved);
}

// round 12
// speedup vs baseline: 1.3144x; 1.3144x over previous
#include <cuda_runtime.h>
#include <cuda_bf16.h>

// ============================================================================
// ESN: FFT(2^18) -> proj(32->50) -> chunked tanh scan -> proj(50->32) -> IFFT.
// R12: radix-8 FFT (3 register-DFT stages, 3x fewer smem ops, padded layout),
// precomputed inter-pass twiddle table (kills 16 sincospif/thread), inv1 GEMM
// 4-rows-per-warp with hoisted weights.
// ============================================================================

#define T_LEN   262144
#define R_DIM   50
#define IN_C    32

#define CH      64      // scan chunk length
#define WARM    32      // warm-up steps per chunk

#define NBUF    (T_LEN * 32)        // 8388608
#define NPROJ   (T_LEN * R_DIM)     // 13107200

// padded in-column index: insert one float2 every 8 -> conflict-free stages
#define PAD(i)  ((i) + ((i) >> 3))
// octal digit reversal of 9-bit index
#define DR(j)   ((((j) & 7) << 6) | ((j) & 56) | ((j) >> 6))
#define CSTR    577                 // column stride (odd, >= PAD(511)+1)

// dynamic smem: float2 sd[32*577] | float2 tw8[512] | float wsm[1600] | float2 ss[128*50]
#define SD_ELEMS   (32 * CSTR)
#define SMEM_FFT   ((SD_ELEMS + 512) * 8)                 // 151808 B
#define SMEM_FUSED (SMEM_FFT + 1600 * 4)                  // 158208 B
#define SMEM_INV1  (SMEM_FUSED + 128 * 50 * 8)            // 209408 B

__device__ float2 g_buf0[NBUF];       // 67 MB (fwd1 -> fwd2)
__device__ float2 g_buf1[NBUF];       // 67 MB (inv1 -> inv2)
__device__ float2 g_proj[NPROJ];      // 105 MB
__device__ float2 g_states[NPROJ];    // 105 MB
__device__ float2 g_twp[512 * 512];   // 2 MB inter-pass twiddles (fwd sign)

// ---------------------------------------------------------------------------
// complex helpers
// ---------------------------------------------------------------------------
__device__ __forceinline__ float2 cadd(float2 a, float2 b){ return make_float2(a.x+b.x, a.y+b.y); }
__device__ __forceinline__ float2 csub(float2 a, float2 b){ return make_float2(a.x-b.x, a.y-b.y); }

template <int SGN>
__device__ __forceinline__ float2 mulJ(float2 v) {   // * (-i) fwd, * (+i) inv
    return (SGN < 0) ? make_float2(v.y, -v.x) : make_float2(-v.y, v.x);
}
// a * W512^(SGN*k), with w = tw8[k] = (cospi(k/256), sinpi(k/256))
template <int SGN>
__device__ __forceinline__ float2 twmul(float2 a, float2 w) {
    return (SGN < 0)
        ? make_float2(fmaf(a.x, w.x,  a.y * w.y), fmaf(a.y, w.x, -a.x * w.y))
        : make_float2(fmaf(a.x, w.x, -a.y * w.y), fmaf(a.y, w.x,  a.x * w.y));
}

// 8-point DFT in registers, natural order in/out. SGN=-1 fwd, +1 inv.
template <int SGN>
__device__ __forceinline__ void dft8(float2* a) {
    const float RS = 0.70710678118654752f;
    float2 e0t = cadd(a[0], a[4]), e1t = csub(a[0], a[4]);
    float2 e2t = cadd(a[2], a[6]), e3t = csub(a[2], a[6]);
    float2 E0 = cadd(e0t, e2t),  E2 = csub(e0t, e2t);
    float2 j3 = mulJ<SGN>(e3t);
    float2 E1 = cadd(e1t, j3),   E3 = csub(e1t, j3);
    float2 o0t = cadd(a[1], a[5]), o1t = csub(a[1], a[5]);
    float2 o2t = cadd(a[3], a[7]), o3t = csub(a[3], a[7]);
    float2 O0 = cadd(o0t, o2t),  O2 = csub(o0t, o2t);
    float2 k3 = mulJ<SGN>(o3t);
    float2 O1 = cadd(o1t, k3),   O3 = csub(o1t, k3);
    float2 T1 = (SGN < 0) ? make_float2(RS*(O1.x+O1.y), RS*(O1.y-O1.x))
                          : make_float2(RS*(O1.x-O1.y), RS*(O1.x+O1.y));
    float2 T2 = mulJ<SGN>(O2);
    float2 T3 = (SGN < 0) ? make_float2(RS*(O3.y-O3.x), RS*(-(O3.x+O3.y)))
                          : make_float2(RS*(-(O3.x+O3.y)), RS*(O3.x-O3.y));
    a[0] = cadd(E0, O0); a[4] = csub(E0, O0);
    a[1] = cadd(E1, T1); a[5] = csub(E1, T1);
    a[2] = cadd(E2, T2); a[6] = csub(E2, T2);
    a[3] = cadd(E3, T3); a[7] = csub(E3, T3);
}

// ---------------------------------------------------------------------------
// 512-pt radix-8 DIT FFT on one padded smem column (input at PAD(DR(j))).
// One warp per column, 2 butterflies/lane/stage, 3 stages.
// ---------------------------------------------------------------------------
template <int SGN>
__device__ __forceinline__ void fft512_r8(float2* s, const float2* tw, int lane) {
    // stage 0: L=1, no twiddles
#pragma unroll
    for (int p = 0; p < 2; ++p) {
        int b = lane + (p << 5);
        float2 a[8];
#pragma unroll
        for (int i = 0; i < 8; ++i) a[i] = s[PAD(b * 8 + i)];
        dft8<SGN>(a);
#pragma unroll
        for (int i = 0; i < 8; ++i) s[PAD(b * 8 + i)] = a[i];
    }
    __syncwarp();
    // stage 1: L=8, twiddle W512^(8*pos*i)
#pragma unroll
    for (int p = 0; p < 2; ++p) {
        int b = lane + (p << 5);
        int g = b >> 3, pos = b & 7;
        int base = g * 64 + pos;
        float2 a[8];
#pragma unroll
        for (int i = 0; i < 8; ++i) a[i] = s[PAD(base + 8 * i)];
#pragma unroll
        for (int i = 1; i < 8; ++i) a[i] = twmul<SGN>(a[i], tw[8 * pos * i]);
        dft8<SGN>(a);
#pragma unroll
        for (int i = 0; i < 8; ++i) s[PAD(base + 8 * i)] = a[i];
    }
    __syncwarp();
    // stage 2: L=64, twiddle W512^(pos*i)
#pragma unroll
    for (int p = 0; p < 2; ++p) {
        int pos = lane + (p << 5);
        float2 a[8];
#pragma unroll
        for (int i = 0; i < 8; ++i) a[i] = s[PAD(pos + 64 * i)];
#pragma unroll
        for (int i = 1; i < 8; ++i) a[i] = twmul<SGN>(a[i], tw[pos * i]);
        dft8<SGN>(a);
#pragma unroll
        for (int i = 0; i < 8; ++i) s[PAD(pos + 64 * i)] = a[i];
    }
    __syncwarp();
}

#define TW8_INIT()                                                           \
    if (tid < 512) {                                                         \
        float swv, cwv;                                                      \
        sincospif((float)tid * (1.0f / 256.0f), &swv, &cwv);                 \
        tw8[tid] = make_float2(cwv, swv);                                    \
    }

// ---------------------------------------------------------------------------
// inter-pass twiddle table: g_twp[n2*512+k1] = sincospif(-(n2*k1)*2^-17)
// ---------------------------------------------------------------------------
__global__ void __launch_bounds__(512) k_twinit(void) {
    int n2 = blockIdx.x, k1 = threadIdx.x;
    float frac = -(float)(n2 * k1) * (2.0f / 262144.f);
    float sw, cw; sincospif(frac, &sw, &cw);
    g_twp[n2 * 512 + k1] = make_float2(cw, sw);
}

// ---------------------------------------------------------------------------
// fwd pass 1: per n2, FFT over n1, inter-pass twiddle (table), store transposed.
// ---------------------------------------------------------------------------
__global__ void __launch_bounds__(1024) k_fwd1(const float* __restrict__ src) {
    extern __shared__ char smraw[];
    float2* sd  = (float2*)smraw;
    float2* tw8 = sd + SD_ELEMS;
    int tid = threadIdx.x;
    TW8_INIT();
    int n2 = blockIdx.x;
    int cc = tid & 31, rb = tid >> 5;
    const float2* twp = g_twp + n2 * 512;

#pragma unroll
    for (int q = 0; q < 16; ++q) {
        int j = rb + (q << 5);
        float v = src[(n2 + (j << 9)) * 32 + cc];
        sd[cc * CSTR + PAD(DR(j))] = make_float2(v, 0.f);
    }
    __syncthreads();

    fft512_r8<-1>(sd + (tid >> 5) * CSTR, tw8, tid & 31);
    __syncthreads();

#pragma unroll
    for (int q = 0; q < 16; ++q) {
        int k1 = rb + (q << 5);
        float2 v = sd[cc * CSTR + PAD(k1)];
        float2 w = twp[k1];
        g_buf0[((k1 << 9) + n2) * 32 + cc] =
            make_float2(v.x * w.x - v.y * w.y, v.x * w.y + v.y * w.x);
    }
}

// ---------------------------------------------------------------------------
// fwd pass 2 + proj fused.
// ---------------------------------------------------------------------------
__global__ void __launch_bounds__(1024) k_fwd2_proj(const float* __restrict__ Win) {
    extern __shared__ char smraw[];
    float2* sd  = (float2*)smraw;
    float2* tw8 = sd + SD_ELEMS;
    float*  wsm = (float*)(tw8 + 512);          // wsm[c*50 + r]
    int tid = threadIdx.x;
    TW8_INIT();
    for (int i = tid; i < R_DIM * 32; i += 1024) {
        int r = i >> 5, c = i & 31;             // Win[r*32+c]
        wsm[c * 50 + r] = Win[i];
    }
    int k1 = blockIdx.x;
    int cc = tid & 31, rb = tid >> 5;

#pragma unroll
    for (int q = 0; q < 16; ++q) {
        int j = rb + (q << 5);
        sd[cc * CSTR + PAD(DR(j))] = g_buf0[((k1 << 9) + j) * 32 + cc];
    }
    __syncthreads();

    fft512_r8<-1>(sd + (tid >> 5) * CSTR, tw8, tid & 31);
    __syncthreads();

    int wid = tid >> 5, lane = tid & 31;
    int r0 = lane;
    int r1c = (lane + 32 < R_DIM) ? lane + 32 : R_DIM - 1;
    bool has1 = (lane + 32 < R_DIM);
    for (int rr = wid; rr < 512; rr += 32) {
        int pr = PAD(rr);
        float ax0 = 0.f, ax1 = 0.f, ax2 = 0.f, ax3 = 0.f;
        float ay0 = 0.f, ay1 = 0.f, ay2 = 0.f, ay3 = 0.f;
        float bx0 = 0.f, bx1 = 0.f, bx2 = 0.f, bx3 = 0.f;
        float by0 = 0.f, by1 = 0.f, by2 = 0.f, by3 = 0.f;
#pragma unroll
        for (int c = 0; c < 32; c += 4) {
            float2 v0 = sd[(c + 0) * CSTR + pr];
            float2 v1 = sd[(c + 1) * CSTR + pr];
            float2 v2 = sd[(c + 2) * CSTR + pr];
            float2 v3 = sd[(c + 3) * CSTR + pr];
            float w0 = wsm[(c + 0) * 50 + r0], u0 = wsm[(c + 0) * 50 + r1c];
            float w1 = wsm[(c + 1) * 50 + r0], u1 = wsm[(c + 1) * 50 + r1c];
            float w2 = wsm[(c + 2) * 50 + r0], u2 = wsm[(c + 2) * 50 + r1c];
            float w3 = wsm[(c + 3) * 50 + r0], u3 = wsm[(c + 3) * 50 + r1c];
            ax0 = fmaf(w0, v0.x, ax0); ay0 = fmaf(w0, v0.y, ay0);
            ax1 = fmaf(w1, v1.x, ax1); ay1 = fmaf(w1, v1.y, ay1);
            ax2 = fmaf(w2, v2.x, ax2); ay2 = fmaf(w2, v2.y, ay2);
            ax3 = fmaf(w3, v3.x, ax3); ay3 = fmaf(w3, v3.y, ay3);
            bx0 = fmaf(u0, v0.x, bx0); by0 = fmaf(u0, v0.y, by0);
            bx1 = fmaf(u1, v1.x, bx1); by1 = fmaf(u1, v1.y, by1);
            bx2 = fmaf(u2, v2.x, bx2); by2 = fmaf(u2, v2.y, by2);
            bx3 = fmaf(u3, v3.x, bx3); by3 = fmaf(u3, v3.y, by3);
        }
        long t = (long)(k1 + (rr << 9));
        g_proj[t * R_DIM + r0] =
            make_float2((ax0 + ax1) + (ax2 + ax3), (ay0 + ay1) + (ay2 + ay3));
        if (has1)
            g_proj[t * R_DIM + lane + 32] =
                make_float2((bx0 + bx1) + (bx2 + bx3), (by0 + by1) + (by2 + by3));
    }
}

// ---------------------------------------------------------------------------
// Chunked reservoir scan (unchanged).
// ---------------------------------------------------------------------------
__device__ __forceinline__ void esn_step(float2 pv, float d, float& sx, float& sy) {
    float zx  = fmaf(d, sx, pv.x);
    float zy  = fmaf(d, sy, pv.y);
    float xcl = fminf(fmaxf(zx, -20.f), 20.f);
    float x2  = xcl + xcl;
    float e   = __expf(x2);
    float em  = __expf(-x2);
    float y2  = zy + zy;
    float kf  = rintf(y2 * 0.15915494309189535f);
    float yr  = fmaf(kf, -6.28125f, y2);
    yr        = fmaf(kf, -1.9353071795864769e-3f, yr);
    float s2, c2; __sincosf(yr, &s2, &c2);
    float den = fmaf(0.5f, e + em, c2);
    float inv = __fdividef(1.f, den);
    sx = 0.5f * (e - em) * inv;
    sy = s2 * inv;
}

__global__ void __launch_bounds__(64) scan_kernel(const float* __restrict__ dv) {
    int r = threadIdx.x;
    if (r >= R_DIM) return;
    float d = dv[r];
    int start = blockIdx.x * CH;
    int ws = start - WARM; if (ws < 0) ws = 0;
    float sx = 0.f, sy = 0.f;

#pragma unroll 4
    for (int t = ws; t < start; ++t) {
        float2 pv = g_proj[t * R_DIM + r];
        esn_step(pv, d, sx, sy);
    }
#pragma unroll 4
    for (int t = start; t < start + CH; ++t) {
        float2 pv = g_proj[t * R_DIM + r];
        esn_step(pv, d, sx, sy);
        g_states[t * R_DIM + r] = make_float2(sx, sy);
    }
}

// ---------------------------------------------------------------------------
// outproj + inv pass 1 fused. 128-row smem tiles; 4 rows/warp with hoisted
// weights (62.5 LDS/row vs 100). Per-output FMA order unchanged.
// ---------------------------------------------------------------------------
__global__ void __launch_bounds__(1024) k_inv1_out(const float* __restrict__ Wout) {
    extern __shared__ char smraw[];
    float2* sd  = (float2*)smraw;
    float2* tw8 = sd + SD_ELEMS;
    float*  wsm = (float*)(tw8 + 512);          // wsm[r*32 + c]
    float2* ss  = (float2*)(wsm + 1600);        // ss[128*50]
    int tid = threadIdx.x;
    TW8_INIT();
    for (int i = tid; i < 32 * R_DIM; i += 1024) {
        int c = i / R_DIM, r = i - c * R_DIM;   // Wout[c*50+r]
        wsm[r * 32 + c] = Wout[i];
    }

    int n2 = blockIdx.x;
    int wid = tid >> 5, lane = tid & 31;        // lane = output column c
    const float2* twp = g_twp + n2 * 512;

    for (int tile = 0; tile < 4; ++tile) {
        int rr0 = tile << 7;                    // 128 rows per tile
        __syncthreads();                        // ss reuse + (tile0) wsm ready
        for (int i = tid; i < 128 * R_DIM; i += 1024) {
            int row = i / R_DIM, r = i - row * R_DIM;
            ss[i] = g_states[(long)(n2 + ((rr0 + row) << 9)) * R_DIM + r];
        }
        __syncthreads();

        int rbase = wid << 2;                   // 4 rows per warp
        const float2* sp0 = ss + (rbase + 0) * R_DIM;
        const float2* sp1 = ss + (rbase + 1) * R_DIM;
        const float2* sp2 = ss + (rbase + 2) * R_DIM;
        const float2* sp3 = ss + (rbase + 3) * R_DIM;
        float ax00=0.f, ax01=0.f, ay00=0.f, ay01=0.f;
        float ax10=0.f, ax11=0.f, ay10=0.f, ay11=0.f;
        float ax20=0.f, ax21=0.f, ay20=0.f, ay21=0.f;
        float ax30=0.f, ax31=0.f, ay30=0.f, ay31=0.f;
#pragma unroll
        for (int r = 0; r < R_DIM; r += 2) {
            float w0 = wsm[r * 32 + lane];
            float w1 = wsm[(r + 1) * 32 + lane];
            float2 v;
            v = sp0[r];     ax00 = fmaf(w0, v.x, ax00); ay00 = fmaf(w0, v.y, ay00);
            v = sp0[r + 1]; ax01 = fmaf(w1, v.x, ax01); ay01 = fmaf(w1, v.y, ay01);
            v = sp1[r];     ax10 = fmaf(w0, v.x, ax10); ay10 = fmaf(w0, v.y, ay10);
            v = sp1[r + 1]; ax11 = fmaf(w1, v.x, ax11); ay11 = fmaf(w1, v.y, ay11);
            v = sp2[r];     ax20 = fmaf(w0, v.x, ax20); ay20 = fmaf(w0, v.y, ay20);
            v = sp2[r + 1]; ax21 = fmaf(w1, v.x, ax21); ay21 = fmaf(w1, v.y, ay21);
            v = sp3[r];     ax30 = fmaf(w0, v.x, ax30); ay30 = fmaf(w0, v.y, ay30);
            v = sp3[r + 1]; ax31 = fmaf(w1, v.x, ax31); ay31 = fmaf(w1, v.y, ay31);
        }
        int ra = rr0 + rbase;
        sd[lane * CSTR + PAD(DR(ra + 0))] = make_float2(ax00 + ax01, ay00 + ay01);
        sd[lane * CSTR + PAD(DR(ra + 1))] = make_float2(ax10 + ax11, ay10 + ay11);
        sd[lane * CSTR + PAD(DR(ra + 2))] = make_float2(ax20 + ax21, ay20 + ay21);
        sd[lane * CSTR + PAD(DR(ra + 3))] = make_float2(ax30 + ax31, ay30 + ay31);
    }
    __syncthreads();

    fft512_r8<1>(sd + (tid >> 5) * CSTR, tw8, tid & 31);
    __syncthreads();

    int cc = tid & 31, rb = tid >> 5;
#pragma unroll
    for (int q = 0; q < 16; ++q) {
        int k1 = rb + (q << 5);
        float2 v = sd[cc * CSTR + PAD(k1)];
        float2 w = twp[k1];                     // inverse = conjugate
        g_buf1[((k1 << 9) + n2) * 32 + cc] =
            make_float2(v.x * w.x + v.y * w.y, v.y * w.x - v.x * w.y);
    }
}

// ---------------------------------------------------------------------------
// inv pass 2: per k1, FFT over contiguous rows, scale 1/N, write d_out.
// ---------------------------------------------------------------------------
__global__ void __launch_bounds__(1024) k_inv2(float* __restrict__ dstf,
                                               int n_out, int interleaved) {
    extern __shared__ char smraw[];
    float2* sd  = (float2*)smraw;
    float2* tw8 = sd + SD_ELEMS;
    int tid = threadIdx.x;
    TW8_INIT();
    int k1 = blockIdx.x;
    int cc = tid & 31, rb = tid >> 5;

#pragma unroll
    for (int q = 0; q < 16; ++q) {
        int j = rb + (q << 5);
        sd[cc * CSTR + PAD(DR(j))] = g_buf1[((k1 << 9) + j) * 32 + cc];
    }
    __syncthreads();

    fft512_r8<1>(sd + (tid >> 5) * CSTR, tw8, tid & 31);
    __syncthreads();

    const float scale = 1.f / 262144.f;
    if (interleaved) {
        float2* d2 = reinterpret_cast<float2*>(dstf);
#pragma unroll
        for (int q = 0; q < 16; ++q) {
            int k2 = rb + (q << 5);
            float2 v = sd[cc * CSTR + PAD(k2)];
            int idx = (k1 + (k2 << 9)) * 32 + cc;
            if (2 * idx + 1 < n_out)
                d2[idx] = make_float2(v.x * scale, v.y * scale);
        }
    } else {
#pragma unroll
        for (int q = 0; q < 16; ++q) {
            int k2 = rb + (q << 5);
            float2 v = sd[cc * CSTR + PAD(k2)];
            int idx = (k1 + (k2 << 9)) * 32 + cc;
            if (idx < n_out)
                dstf[idx] = v.x * scale;
        }
    }
}

// ---------------------------------------------------------------------------
extern "C" void kernel_launch(void* const* d_in, const int* in_sizes, int n_in,
                              void* d_out, int out_size) {
    const float* X    = nullptr;
    const float* Win  = nullptr;
    const float* dres = nullptr;
    const float* Wout = nullptr;
    for (int i = 0; i < n_in; ++i) {
        int sz = in_sizes[i];
        const float* p = (const float*)d_in[i];
        if (sz == T_LEN * IN_C && !X)          X = p;
        else if (sz == R_DIM && !dres)         dres = p;
        else if (sz == R_DIM * IN_C)           { if (!Win) Win = p; else if (!Wout) Wout = p; }
    }
    if ((!X || !Win || !dres || !Wout) && n_in >= 4) {
        X    = (const float*)d_in[0];
        Win  = (const float*)d_in[1];
        dres = (const float*)d_in[2];
        Wout = (const float*)d_in[3];
        if (in_sizes[0] != T_LEN * IN_C) { X = nullptr; }
    }
    if (!X || !Win || !dres || !Wout || !d_out)
        return;   // fail-closed

    int interleaved = (out_size >= 2 * NBUF) ? 1 : 0;

    cudaFuncSetAttribute(k_fwd1,      cudaFuncAttributeMaxDynamicSharedMemorySize, SMEM_FFT);
    cudaFuncSetAttribute(k_fwd2_proj, cudaFuncAttributeMaxDynamicSharedMemorySize, SMEM_FUSED);
    cudaFuncSetAttribute(k_inv1_out,  cudaFuncAttributeMaxDynamicSharedMemorySize, SMEM_INV1);
    cudaFuncSetAttribute(k_inv2,      cudaFuncAttributeMaxDynamicSharedMemorySize, SMEM_FFT);

    k_twinit<<<512, 512>>>();                              // 2MB twiddle table
    k_fwd1<<<512, 1024, SMEM_FFT>>>(X);                    // X -> buf0
    k_fwd2_proj<<<512, 1024, SMEM_FUSED>>>(Win);           // buf0 -> g_proj
    scan_kernel<<<T_LEN / CH, 64>>>(dres);                 // g_proj -> g_states
    k_inv1_out<<<512, 1024, SMEM_INV1>>>(Wout);            // g_states -> buf1
    k_inv2<<<512, 1024, SMEM_FFT>>>((float*)d_out, out_size, interleaved);
}